// round 1
// baseline (speedup 1.0000x reference)
#include <cuda_runtime.h>
#include <math.h>

#define B_ 8
#define S_ 1024
#define D_ 256
#define H_ 8
#define DH_ 32
#define BH_ (B_*H_)
#define ROWS 32
#define JC 128
#define SS_STRIDE 1025

// Scratch (device globals: no allocation allowed)
__device__ float g_Qp[BH_*S_*DH_];   // [B,H,S,DH]
__device__ float g_Kp[BH_*S_*DH_];
__device__ float g_Vp[BH_*S_*DH_];
__device__ float g_ctx[B_*S_*D_];    // attention output, [B,S,D]

// ---------------------------------------------------------------------------
// GEMM: C[m,n] = sum_k A[m,k] * W[n,k] + bias[n]   (M=8192, N=K=256)
// headLayout=1 -> write [B,H,S,DH]; else row-major [M,N]
// ---------------------------------------------------------------------------
__global__ __launch_bounds__(256) void gemm_bias_kernel(
    const float* __restrict__ A, const float* __restrict__ W,
    const float* __restrict__ bias, float* __restrict__ C, int headLayout)
{
    __shared__ float sA[16][65];
    __shared__ float sW[16][65];
    const int K = D_;
    int tid = threadIdx.x;
    int tx = tid & 15, ty = tid >> 4;
    int m0 = blockIdx.y * 64, n0 = blockIdx.x * 64;
    int lr = tid >> 2, lc = (tid & 3) * 4;
    float acc[4][4] = {};
    for (int k0 = 0; k0 < K; k0 += 16) {
        float4 av = *(const float4*)&A[(size_t)(m0 + lr) * K + k0 + lc];
        float4 wv = *(const float4*)&W[(size_t)(n0 + lr) * K + k0 + lc];
        sA[lc+0][lr] = av.x; sA[lc+1][lr] = av.y; sA[lc+2][lr] = av.z; sA[lc+3][lr] = av.w;
        sW[lc+0][lr] = wv.x; sW[lc+1][lr] = wv.y; sW[lc+2][lr] = wv.z; sW[lc+3][lr] = wv.w;
        __syncthreads();
        #pragma unroll
        for (int kk = 0; kk < 16; kk++) {
            float a[4], b[4];
            #pragma unroll
            for (int i = 0; i < 4; i++) a[i] = sA[kk][ty*4 + i];
            #pragma unroll
            for (int j = 0; j < 4; j++) b[j] = sW[kk][tx*4 + j];
            #pragma unroll
            for (int i = 0; i < 4; i++)
                #pragma unroll
                for (int j = 0; j < 4; j++)
                    acc[i][j] = fmaf(a[i], b[j], acc[i][j]);
        }
        __syncthreads();
    }
    #pragma unroll
    for (int i = 0; i < 4; i++) {
        int m = m0 + ty*4 + i;
        int bb = m >> 10, ss = m & 1023;
        #pragma unroll
        for (int j = 0; j < 4; j++) {
            int n = n0 + tx*4 + j;
            float val = acc[i][j] + bias[n];
            if (headLayout) {
                int h = n >> 5, dh = n & 31;
                C[(((size_t)(bb*H_ + h) * S_) + ss) * DH_ + dh] = val;
            } else {
                C[(size_t)m * D_ + n] = val;
            }
        }
    }
}

// ---------------------------------------------------------------------------
// Fused attention: per block = one (b,h) and 32 query rows.
//  QK^T -> softmax -> cumsum -> distance decay -> softmax -> scores out + PV
// ---------------------------------------------------------------------------
#define SMEM_BYTES ((ROWS*SS_STRIDE + ROWS*DH_ + 32*33*4) * 4)

__global__ __launch_bounds__(256) void attn_kernel(
    const float* __restrict__ gammas, float* __restrict__ scores_out)
{
    extern __shared__ float smem[];
    float* sS  = smem;                          // [32][1025] score rows
    float* sQ  = sS + ROWS * SS_STRIDE;         // [32][32]
    float* sKV = sQ + ROWS * DH_;               // 4224 floats: K^T tile / V tile
    int tid = threadIdx.x;
    int lane = tid & 31, warp = tid >> 5;
    int bh = blockIdx.y;
    int q0 = blockIdx.x * ROWS;
    int h = bh & (H_ - 1);
    int b = bh >> 3;
    const float* Q  = g_Qp + (size_t)bh * S_ * DH_;
    const float* Kp = g_Kp + (size_t)bh * S_ * DH_;
    const float* Vp = g_Vp + (size_t)bh * S_ * DH_;

    // Q tile, pre-scaled by 1/sqrt(DH)
    for (int i = tid; i < ROWS * DH_; i += 256)
        sQ[i] = Q[q0 * DH_ + i] * 0.17677669529663688f;

    int nch = (q0 + ROWS + JC - 1) / JC;  // causal: only chunks up to q0+31
    int rg = tid >> 5, cg = tid & 31;

    // ---- QK^T into sS ----
    for (int ch = 0; ch < nch; ch++) {
        int jb = ch * JC;
        __syncthreads();
        // stage K chunk transposed: float4 tile [d][jgroup] (33 stride)
        for (int f = tid; f < JC * DH_ / 4; f += 256) {
            int j = f >> 3, d0 = (f & 7) << 2;
            float4 kv = *(const float4*)&Kp[(size_t)(jb + j) * DH_ + d0];
            int jg = j >> 2, jc = j & 3;
            sKV[((d0+0)*33 + jg)*4 + jc] = kv.x;
            sKV[((d0+1)*33 + jg)*4 + jc] = kv.y;
            sKV[((d0+2)*33 + jg)*4 + jc] = kv.z;
            sKV[((d0+3)*33 + jg)*4 + jc] = kv.w;
        }
        __syncthreads();
        float acc[4][4] = {};
        const float4* sKT4 = (const float4*)sKV;
        #pragma unroll
        for (int d = 0; d < DH_; d++) {
            float4 b4 = sKT4[d*33 + cg];
            #pragma unroll
            for (int i = 0; i < 4; i++) {
                float a = sQ[(rg*4 + i) * DH_ + d];
                acc[i][0] = fmaf(a, b4.x, acc[i][0]);
                acc[i][1] = fmaf(a, b4.y, acc[i][1]);
                acc[i][2] = fmaf(a, b4.z, acc[i][2]);
                acc[i][3] = fmaf(a, b4.w, acc[i][3]);
            }
        }
        #pragma unroll
        for (int i = 0; i < 4; i++)
            #pragma unroll
            for (int j = 0; j < 4; j++)
                sS[(rg*4 + i) * SS_STRIDE + jb + cg*4 + j] = acc[i][j];
    }
    __syncthreads();

    // ---- row-wise: softmax, cumsum scan, decay, 2nd softmax, write scores ----
    float gam = -fabsf(gammas[h]);
    for (int rr = 0; rr < 4; rr++) {
        int r = warp + rr * 8;
        int qg = q0 + r;
        int L = qg + 1;
        float* row = sS + r * SS_STRIDE;

        float m1 = -INFINITY;
        for (int j = lane; j < L; j += 32) m1 = fmaxf(m1, row[j]);
        #pragma unroll
        for (int o = 16; o; o >>= 1) m1 = fmaxf(m1, __shfl_xor_sync(0xffffffffu, m1, o));

        float Z1 = 0.f;
        for (int j = lane; j < L; j += 32) Z1 += __expf(row[j] - m1);
        #pragma unroll
        for (int o = 16; o; o >>= 1) Z1 += __shfl_xor_sync(0xffffffffu, Z1, o);
        float invZ1 = __frcp_rn(Z1);

        // scan: cum of exp; rem = 1 - cum/Z; dist = sqrt(rem * |q-j|); s2 = s*eff
        float running = 0.f, m2 = -INFINITY;
        for (int jb = 0; jb < L; jb += 32) {
            int j = jb + lane;
            float s = (j < L) ? row[j] : 0.f;
            float e = (j < L) ? __expf(s - m1) : 0.f;
            float c = e;
            #pragma unroll
            for (int o = 1; o < 32; o <<= 1) {
                float t = __shfl_up_sync(0xffffffffu, c, o);
                if (lane >= o) c += t;
            }
            float cum = running + c;
            running += __shfl_sync(0xffffffffu, c, 31);
            if (j < L) {
                float rem = 1.f - cum * invZ1;
                float pos = (float)(qg - j);
                float dist = sqrtf(fmaxf(rem * pos, 0.f));
                float eff = fmaxf(__expf(gam * dist), 1e-5f);  // eff<=1 so upper clip moot
                float s2 = s * eff;
                row[j] = s2;
                m2 = fmaxf(m2, s2);
            }
        }
        #pragma unroll
        for (int o = 16; o; o >>= 1) m2 = fmaxf(m2, __shfl_xor_sync(0xffffffffu, m2, o));

        float Z2 = 0.f;
        for (int j = lane; j < L; j += 32) Z2 += __expf(row[j] - m2);
        #pragma unroll
        for (int o = 16; o; o >>= 1) Z2 += __shfl_xor_sync(0xffffffffu, Z2, o);
        float invZ2 = __frcp_rn(Z2);

        float* grow = scores_out + ((size_t)bh * S_ + qg) * S_;
        for (int j = lane; j < S_; j += 32) {
            float p = (j < L) ? __expf(row[j] - m2) * invZ2 : 0.f;
            row[j] = p;       // p in shared for PV (zeros in masked region)
            grow[j] = p;      // scores output (masked == exact 0, matches ref)
        }
    }

    // ---- PV: ctx = P @ V, V staged in shared, reused by all 32 rows ----
    float acc[4] = {0.f, 0.f, 0.f, 0.f};
    for (int ch = 0; ch < nch; ch++) {
        int jb = ch * JC;
        __syncthreads();
        for (int f = tid; f < JC * DH_ / 4; f += 256) {
            int j = f >> 3, d0 = (f & 7) << 2;
            *(float4*)&sKV[j * DH_ + d0] = *(const float4*)&Vp[(size_t)(jb + j) * DH_ + d0];
        }
        __syncthreads();
        #pragma unroll 4
        for (int j = 0; j < JC; j++) {
            float v = sKV[j * DH_ + lane];
            acc[0] = fmaf(sS[(warp     ) * SS_STRIDE + jb + j], v, acc[0]);
            acc[1] = fmaf(sS[(warp +  8) * SS_STRIDE + jb + j], v, acc[1]);
            acc[2] = fmaf(sS[(warp + 16) * SS_STRIDE + jb + j], v, acc[2]);
            acc[3] = fmaf(sS[(warp + 24) * SS_STRIDE + jb + j], v, acc[3]);
        }
    }
    #pragma unroll
    for (int rr = 0; rr < 4; rr++) {
        int qg = q0 + warp + rr * 8;
        g_ctx[((size_t)(b * S_ + qg)) * D_ + h * DH_ + lane] = acc[rr];
    }
}

// ---------------------------------------------------------------------------
extern "C" void kernel_launch(void* const* d_in, const int* in_sizes, int n_in,
                              void* d_out, int out_size) {
    const float* q      = (const float*)d_in[0];
    const float* k      = (const float*)d_in[1];
    const float* v      = (const float*)d_in[2];
    // d_in[3] = mask (causal, known at compile time) -- unused
    const float* Wq     = (const float*)d_in[4];
    const float* bq     = (const float*)d_in[5];
    const float* Wv     = (const float*)d_in[6];
    const float* bv     = (const float*)d_in[7];
    const float* Wo     = (const float*)d_in[8];
    const float* bo     = (const float*)d_in[9];
    const float* gammas = (const float*)d_in[10];

    float* out    = (float*)d_out;                       // [B,S,D]
    float* scores = out + (size_t)B_ * S_ * D_;          // [B,H,S,S]

    float *Qp, *Kp, *Vp, *ctx;
    cudaGetSymbolAddress((void**)&Qp,  g_Qp);
    cudaGetSymbolAddress((void**)&Kp,  g_Kp);
    cudaGetSymbolAddress((void**)&Vp,  g_Vp);
    cudaGetSymbolAddress((void**)&ctx, g_ctx);

    dim3 ggrid(4, 128);
    gemm_bias_kernel<<<ggrid, 256>>>(q, Wq, bq, Qp, 1);
    gemm_bias_kernel<<<ggrid, 256>>>(k, Wq, bq, Kp, 1);
    gemm_bias_kernel<<<ggrid, 256>>>(v, Wv, bv, Vp, 1);

    cudaFuncSetAttribute(attn_kernel, cudaFuncAttributeMaxDynamicSharedMemorySize, SMEM_BYTES);
    attn_kernel<<<dim3(S_ / ROWS, BH_), 256, SMEM_BYTES>>>(gammas, scores);

    gemm_bias_kernel<<<ggrid, 256>>>(ctx, Wo, bo, out, 0);
}

// round 2
// speedup vs baseline: 1.3616x; 1.3616x over previous
#include <cuda_runtime.h>
#include <math.h>

#define B_ 8
#define S_ 1024
#define D_ 256
#define H_ 8
#define DH_ 32
#define BH_ (B_*H_)
#define ROWS 32
#define JC 128
#define SS_STRIDE 1028
#define THREADS 512

// Scratch (device globals: no allocation allowed)
__device__ float g_Qp[BH_*S_*DH_];   // [B,H,S,DH]
__device__ float g_Kp[BH_*S_*DH_];
__device__ float g_Vp[BH_*S_*DH_];
__device__ float g_ctx[B_*S_*D_];    // attention output, [B,S,D]

// ---------------------------------------------------------------------------
// GEMM: C[m,n] = sum_k A[m,k] * W[n,k] + bias[n]   (M=8192, N=K=256)
// headLayout=1 -> write [B,H,S,DH]; else row-major [M,N]
// ---------------------------------------------------------------------------
__global__ __launch_bounds__(256) void gemm_bias_kernel(
    const float* __restrict__ A, const float* __restrict__ W,
    const float* __restrict__ bias, float* __restrict__ C, int headLayout)
{
    __shared__ float sA[16][65];
    __shared__ float sW[16][65];
    const int K = D_;
    int tid = threadIdx.x;
    int tx = tid & 15, ty = tid >> 4;
    int m0 = blockIdx.y * 64, n0 = blockIdx.x * 64;
    int lr = tid >> 2, lc = (tid & 3) * 4;
    float acc[4][4] = {};
    for (int k0 = 0; k0 < K; k0 += 16) {
        float4 av = *(const float4*)&A[(size_t)(m0 + lr) * K + k0 + lc];
        float4 wv = *(const float4*)&W[(size_t)(n0 + lr) * K + k0 + lc];
        sA[lc+0][lr] = av.x; sA[lc+1][lr] = av.y; sA[lc+2][lr] = av.z; sA[lc+3][lr] = av.w;
        sW[lc+0][lr] = wv.x; sW[lc+1][lr] = wv.y; sW[lc+2][lr] = wv.z; sW[lc+3][lr] = wv.w;
        __syncthreads();
        #pragma unroll
        for (int kk = 0; kk < 16; kk++) {
            float a[4], b[4];
            #pragma unroll
            for (int i = 0; i < 4; i++) a[i] = sA[kk][ty*4 + i];
            #pragma unroll
            for (int j = 0; j < 4; j++) b[j] = sW[kk][tx*4 + j];
            #pragma unroll
            for (int i = 0; i < 4; i++)
                #pragma unroll
                for (int j = 0; j < 4; j++)
                    acc[i][j] = fmaf(a[i], b[j], acc[i][j]);
        }
        __syncthreads();
    }
    #pragma unroll
    for (int i = 0; i < 4; i++) {
        int m = m0 + ty*4 + i;
        int bb = m >> 10, ss = m & 1023;
        #pragma unroll
        for (int j = 0; j < 4; j++) {
            int n = n0 + tx*4 + j;
            float val = acc[i][j] + bias[n];
            if (headLayout) {
                int h = n >> 5, dh = n & 31;
                C[(((size_t)(bb*H_ + h) * S_) + ss) * DH_ + dh] = val;
            } else {
                C[(size_t)m * D_ + n] = val;
            }
        }
    }
}

// ---------------------------------------------------------------------------
// Fused attention: per block = one (b,h) and 32 query rows, 512 threads.
// ---------------------------------------------------------------------------
#define SMEM_FLOATS (ROWS*SS_STRIDE + ROWS*DH_ + 32*33*4)
#define SMEM_BYTES (SMEM_FLOATS * 4)

__global__ __launch_bounds__(THREADS) void attn_kernel(
    const float* __restrict__ gammas, float* __restrict__ scores_out)
{
    extern __shared__ float smem[];
    float* sS  = smem;                          // [32][1028] score rows
    float* sQ  = sS + ROWS * SS_STRIDE;         // [32][32]
    float* sKV = sQ + ROWS * DH_;               // 4224 floats: K^T tile / V tile
    int tid = threadIdx.x;
    int lane = tid & 31, warp = tid >> 5;       // 16 warps
    int bh = blockIdx.y;
    int q0 = blockIdx.x * ROWS;
    int h = bh & (H_ - 1);
    int b = bh >> 3;
    const float* Q  = g_Qp + (size_t)bh * S_ * DH_;
    const float* Kp = g_Kp + (size_t)bh * S_ * DH_;
    const float* Vp = g_Vp + (size_t)bh * S_ * DH_;

    // Q tile, pre-scaled by 1/sqrt(DH)
    for (int i = tid; i < ROWS * DH_; i += THREADS)
        sQ[i] = Q[q0 * DH_ + i] * 0.17677669529663688f;

    int nch = (q0 + ROWS + JC - 1) / JC;

    // ---- QK^T into sS : each thread -> rows {warp, warp+16}, cols lane*4..+3 of chunk ----
    for (int ch = 0; ch < nch; ch++) {
        int jb = ch * JC;
        __syncthreads();
        // stage K chunk transposed: float4 tile [d][jgroup], stride 33 groups
        for (int f = tid; f < JC * DH_ / 4; f += THREADS) {
            int j = f >> 3, d0 = (f & 7) << 2;
            float4 kv = *(const float4*)&Kp[(size_t)(jb + j) * DH_ + d0];
            int jg = j >> 2, jc = j & 3;
            sKV[((d0+0)*33 + jg)*4 + jc] = kv.x;
            sKV[((d0+1)*33 + jg)*4 + jc] = kv.y;
            sKV[((d0+2)*33 + jg)*4 + jc] = kv.z;
            sKV[((d0+3)*33 + jg)*4 + jc] = kv.w;
        }
        __syncthreads();
        float4 acc0 = {0,0,0,0}, acc1 = {0,0,0,0};
        const float4* sKT4 = (const float4*)sKV;
        const float* q0p = sQ + warp * DH_;
        const float* q1p = sQ + (warp + 16) * DH_;
        #pragma unroll
        for (int d = 0; d < DH_; d++) {
            float4 b4 = sKT4[d*33 + lane];
            float a0 = q0p[d], a1 = q1p[d];
            acc0.x = fmaf(a0, b4.x, acc0.x); acc0.y = fmaf(a0, b4.y, acc0.y);
            acc0.z = fmaf(a0, b4.z, acc0.z); acc0.w = fmaf(a0, b4.w, acc0.w);
            acc1.x = fmaf(a1, b4.x, acc1.x); acc1.y = fmaf(a1, b4.y, acc1.y);
            acc1.z = fmaf(a1, b4.z, acc1.z); acc1.w = fmaf(a1, b4.w, acc1.w);
        }
        *(float4*)&sS[(size_t)warp * SS_STRIDE + jb + lane*4] = acc0;
        *(float4*)&sS[(size_t)(warp+16) * SS_STRIDE + jb + lane*4] = acc1;
    }
    __syncthreads();

    // ---- row-wise: softmax, scan, decay, 2nd softmax, write scores ----
    float gam = -fabsf(gammas[h]);
    #pragma unroll
    for (int rr = 0; rr < 2; rr++) {
        int r = warp + rr * 16;
        int qg = q0 + r;
        int L = qg + 1;
        float* row = sS + (size_t)r * SS_STRIDE;

        float m1 = -INFINITY;
        for (int j = lane; j < L; j += 32) m1 = fmaxf(m1, row[j]);
        #pragma unroll
        for (int o = 16; o; o >>= 1) m1 = fmaxf(m1, __shfl_xor_sync(0xffffffffu, m1, o));

        float Z1 = 0.f;
        for (int j = lane; j < L; j += 32) Z1 += __expf(row[j] - m1);
        #pragma unroll
        for (int o = 16; o; o >>= 1) Z1 += __shfl_xor_sync(0xffffffffu, Z1, o);
        float invZ1 = __frcp_rn(Z1);

        // scan: cumsum of exp; rem = 1 - cum/Z; dist = sqrt(rem*|q-j|); s2 = s*eff
        float running = 0.f, m2 = -INFINITY;
        for (int jb = 0; jb < L; jb += 32) {
            int j = jb + lane;
            float s = (j < L) ? row[j] : 0.f;
            float e = (j < L) ? __expf(s - m1) : 0.f;
            float c = e;
            #pragma unroll
            for (int o = 1; o < 32; o <<= 1) {
                float t = __shfl_up_sync(0xffffffffu, c, o);
                if (lane >= o) c += t;
            }
            float cum = running + c;
            running += __shfl_sync(0xffffffffu, c, 31);
            if (j < L) {
                float rem = 1.f - cum * invZ1;
                float pos = (float)(qg - j);
                float dist = sqrtf(fmaxf(rem * pos, 0.f));
                float eff = fmaxf(__expf(gam * dist), 1e-5f);
                float s2 = s * eff;
                row[j] = s2;
                m2 = fmaxf(m2, s2);
            }
        }
        #pragma unroll
        for (int o = 16; o; o >>= 1) m2 = fmaxf(m2, __shfl_xor_sync(0xffffffffu, m2, o));

        float Z2 = 0.f;
        for (int j = lane; j < L; j += 32) Z2 += __expf(row[j] - m2);
        #pragma unroll
        for (int o = 16; o; o >>= 1) Z2 += __shfl_xor_sync(0xffffffffu, Z2, o);
        float invZ2 = __frcp_rn(Z2);

        float* grow = scores_out + ((size_t)bh * S_ + qg) * S_;
        for (int j4 = lane; j4 < S_/4; j4 += 32) {
            int j = j4 * 4;
            float4 sv = *(const float4*)&row[j];
            float4 p;
            p.x = (j+0 < L) ? __expf(sv.x - m2) * invZ2 : 0.f;
            p.y = (j+1 < L) ? __expf(sv.y - m2) * invZ2 : 0.f;
            p.z = (j+2 < L) ? __expf(sv.z - m2) * invZ2 : 0.f;
            p.w = (j+3 < L) ? __expf(sv.w - m2) * invZ2 : 0.f;
            *(float4*)&row[j] = p;        // for PV (zeros in masked region)
            *(float4*)&grow[j] = p;       // scores output
        }
    }

    // ---- PV: ctx = P @ V ; rows {warp, warp+16}, dim = lane ----
    float acc0 = 0.f, acc1 = 0.f;
    const float* row0 = sS + (size_t)warp * SS_STRIDE;
    const float* row1 = sS + (size_t)(warp+16) * SS_STRIDE;
    for (int ch = 0; ch < nch; ch++) {
        int jb = ch * JC;
        __syncthreads();
        for (int f = tid; f < JC * DH_ / 4; f += THREADS) {
            int j = f >> 3, d0 = (f & 7) << 2;
            *(float4*)&sKV[j * DH_ + d0] = *(const float4*)&Vp[(size_t)(jb + j) * DH_ + d0];
        }
        __syncthreads();
        #pragma unroll 8
        for (int j = 0; j < JC; j++) {
            float v = sKV[j * DH_ + lane];
            acc0 = fmaf(row0[jb + j], v, acc0);
            acc1 = fmaf(row1[jb + j], v, acc1);
        }
    }
    {
        int qg0 = q0 + warp, qg1 = q0 + warp + 16;
        g_ctx[((size_t)(b * S_ + qg0)) * D_ + h * DH_ + lane] = acc0;
        g_ctx[((size_t)(b * S_ + qg1)) * D_ + h * DH_ + lane] = acc1;
    }
}

// ---------------------------------------------------------------------------
extern "C" void kernel_launch(void* const* d_in, const int* in_sizes, int n_in,
                              void* d_out, int out_size) {
    const float* q      = (const float*)d_in[0];
    const float* k      = (const float*)d_in[1];
    const float* v      = (const float*)d_in[2];
    const float* Wq     = (const float*)d_in[4];
    const float* bq     = (const float*)d_in[5];
    const float* Wv     = (const float*)d_in[6];
    const float* bv     = (const float*)d_in[7];
    const float* Wo     = (const float*)d_in[8];
    const float* bo     = (const float*)d_in[9];
    const float* gammas = (const float*)d_in[10];

    float* out    = (float*)d_out;                       // [B,S,D]
    float* scores = out + (size_t)B_ * S_ * D_;          // [B,H,S,S]

    float *Qp, *Kp, *Vp, *ctx;
    cudaGetSymbolAddress((void**)&Qp,  g_Qp);
    cudaGetSymbolAddress((void**)&Kp,  g_Kp);
    cudaGetSymbolAddress((void**)&Vp,  g_Vp);
    cudaGetSymbolAddress((void**)&ctx, g_ctx);

    dim3 ggrid(4, 128);
    gemm_bias_kernel<<<ggrid, 256>>>(q, Wq, bq, Qp, 1);
    gemm_bias_kernel<<<ggrid, 256>>>(k, Wq, bq, Kp, 1);
    gemm_bias_kernel<<<ggrid, 256>>>(v, Wv, bv, Vp, 1);

    cudaFuncSetAttribute(attn_kernel, cudaFuncAttributeMaxDynamicSharedMemorySize, SMEM_BYTES);
    attn_kernel<<<dim3(S_ / ROWS, BH_), THREADS, SMEM_BYTES>>>(gammas, scores);

    gemm_bias_kernel<<<ggrid, 256>>>(ctx, Wo, bo, out, 0);
}

// round 3
// speedup vs baseline: 1.5889x; 1.1669x over previous
#include <cuda_runtime.h>
#include <math.h>

#define B_ 8
#define S_ 1024
#define D_ 256
#define H_ 8
#define DH_ 32
#define BH_ (B_*H_)
#define ROWS 32
#define JC 128
#define SS_STRIDE 1028
#define THREADS 512

// Scratch (device globals: no allocation allowed)
__device__ float g_Qp[BH_*S_*DH_];   // [B,H,S,DH]
__device__ float g_Kp[BH_*S_*DH_];
__device__ float g_Vp[BH_*S_*DH_];
__device__ float g_ctx[B_*S_*D_];    // attention output, [B,S,D]

// ---------------------------------------------------------------------------
// GEMM: C[m,n] = sum_k A[m,k] * W[n,k] + bias[n]   (M=8192, N=K=256)
// ---------------------------------------------------------------------------
__global__ __launch_bounds__(256) void gemm_bias_kernel(
    const float* __restrict__ A, const float* __restrict__ W,
    const float* __restrict__ bias, float* __restrict__ C, int headLayout)
{
    __shared__ float sA[16][68];
    __shared__ float sW[16][68];
    const int K = D_;
    int tid = threadIdx.x;
    int tx = tid & 15, ty = tid >> 4;
    int m0 = blockIdx.y * 64, n0 = blockIdx.x * 64;
    int lr = tid >> 2, lc = (tid & 3) * 4;
    float acc[4][4] = {};
    for (int k0 = 0; k0 < K; k0 += 16) {
        float4 av = *(const float4*)&A[(size_t)(m0 + lr) * K + k0 + lc];
        float4 wv = *(const float4*)&W[(size_t)(n0 + lr) * K + k0 + lc];
        sA[lc+0][lr] = av.x; sA[lc+1][lr] = av.y; sA[lc+2][lr] = av.z; sA[lc+3][lr] = av.w;
        sW[lc+0][lr] = wv.x; sW[lc+1][lr] = wv.y; sW[lc+2][lr] = wv.z; sW[lc+3][lr] = wv.w;
        __syncthreads();
        #pragma unroll
        for (int kk = 0; kk < 16; kk++) {
            float4 a4 = *(const float4*)&sA[kk][ty*4];
            float4 b4 = *(const float4*)&sW[kk][tx*4];
            float a[4] = {a4.x, a4.y, a4.z, a4.w};
            float b[4] = {b4.x, b4.y, b4.z, b4.w};
            #pragma unroll
            for (int i = 0; i < 4; i++)
                #pragma unroll
                for (int j = 0; j < 4; j++)
                    acc[i][j] = fmaf(a[i], b[j], acc[i][j]);
        }
        __syncthreads();
    }
    #pragma unroll
    for (int i = 0; i < 4; i++) {
        int m = m0 + ty*4 + i;
        int bb = m >> 10, ss = m & 1023;
        #pragma unroll
        for (int j = 0; j < 4; j++) {
            int n = n0 + tx*4 + j;
            float val = acc[i][j] + bias[n];
            if (headLayout) {
                int h = n >> 5, dh = n & 31;
                C[(((size_t)(bb*H_ + h) * S_) + ss) * DH_ + dh] = val;
            } else {
                C[(size_t)m * D_ + n] = val;
            }
        }
    }
}

// ---------------------------------------------------------------------------
// Fused attention: per block = one (b,h) and 32 query rows, 512 threads.
// smem: sS[32][1028] rows | sQ[32][32] swz | sKV[128][32] swz | sRed[8][1024]
// ---------------------------------------------------------------------------
#define SQ_OFF   (ROWS * SS_STRIDE)
#define SKV_OFF  (SQ_OFF + ROWS * 32)
#define SRED_OFF (SKV_OFF + JC * 32)
#define SMEM_FLOATS (SRED_OFF + 8 * 1024)
#define SMEM_BYTES (SMEM_FLOATS * 4)

__global__ __launch_bounds__(THREADS) void attn_kernel(
    const float* __restrict__ gammas, float* __restrict__ scores_out)
{
    extern __shared__ float smem[];
    float* sS   = smem;
    float* sQ   = smem + SQ_OFF;
    float* sKV  = smem + SKV_OFF;
    float* sRed = smem + SRED_OFF;
    int tid = threadIdx.x;
    int lane = tid & 31, warp = tid >> 5;       // 16 warps
    int bh = blockIdx.y;
    int q0 = blockIdx.x * ROWS;
    int h = bh & (H_ - 1);
    int b = bh >> 3;
    const float* Q  = g_Qp + (size_t)bh * S_ * DH_;
    const float* Kp = g_Kp + (size_t)bh * S_ * DH_;
    const float* Vp = g_Vp + (size_t)bh * S_ * DH_;

    // ---- stage Q (scaled), swizzled: d4eff = d4 ^ ((row>>2)&7) ----
    for (int f = tid; f < ROWS * 8; f += THREADS) {
        int r = f >> 3, d4 = f & 7;
        float4 qv = *(const float4*)&Q[(size_t)(q0 + r) * DH_ + d4 * 4];
        const float sc = 0.17677669529663688f;
        qv.x *= sc; qv.y *= sc; qv.z *= sc; qv.w *= sc;
        int d4e = d4 ^ ((r >> 2) & 7);
        *(float4*)&sQ[r * 32 + d4e * 4] = qv;
    }

    int nch = (q0 + ROWS + JC - 1) / JC;

    // QK tiling: warp -> 16 rows (warp&1) x 16 cols (warp>>1); thread 4x2
    int rowHalf = warp & 1;
    int colSeg  = warp >> 1;
    int rg = lane >> 3, cg = lane & 7;
    int r0 = rowHalf * 16 + rg * 4;
    int c0 = colSeg * 16 + cg * 2;

    // ---- QK^T into sS ----
    for (int ch = 0; ch < nch; ch++) {
        int jb = ch * JC;
        __syncthreads();
        // stage K chunk natural [j][d], swizzled d4eff = d4 ^ ((j>>1)&7)
        for (int f = tid; f < JC * 8; f += THREADS) {
            int j = f >> 3, d4 = f & 7;
            float4 kv = *(const float4*)&Kp[(size_t)(jb + j) * DH_ + d4 * 4];
            int d4e = d4 ^ ((j >> 1) & 7);
            *(float4*)&sKV[j * 32 + d4e * 4] = kv;
        }
        __syncthreads();
        float acc[4][2] = {};
        #pragma unroll
        for (int d4 = 0; d4 < 8; d4++) {
            float4 q4[4];
            #pragma unroll
            for (int r = 0; r < 4; r++) {
                int row = r0 + r;
                q4[r] = *(const float4*)&sQ[row * 32 + ((d4 ^ ((row >> 2) & 7)) << 2)];
            }
            #pragma unroll
            for (int c = 0; c < 2; c++) {
                int jj = c0 + c;
                float4 k4 = *(const float4*)&sKV[jj * 32 + ((d4 ^ ((jj >> 1) & 7)) << 2)];
                #pragma unroll
                for (int r = 0; r < 4; r++) {
                    acc[r][c] = fmaf(q4[r].x, k4.x, acc[r][c]);
                    acc[r][c] = fmaf(q4[r].y, k4.y, acc[r][c]);
                    acc[r][c] = fmaf(q4[r].z, k4.z, acc[r][c]);
                    acc[r][c] = fmaf(q4[r].w, k4.w, acc[r][c]);
                }
            }
        }
        #pragma unroll
        for (int r = 0; r < 4; r++) {
            float2 st = make_float2(acc[r][0], acc[r][1]);
            *(float2*)&sS[(size_t)(r0 + r) * SS_STRIDE + jb + c0] = st;
        }
    }
    __syncthreads();

    // ---- row-wise: softmax, scan, decay, 2nd softmax, write scores ----
    float gam = -fabsf(gammas[h]);
    #pragma unroll
    for (int rr = 0; rr < 2; rr++) {
        int r = warp + rr * 16;
        int qg = q0 + r;
        int L = qg + 1;
        float* row = sS + (size_t)r * SS_STRIDE;

        float m1 = -INFINITY;
        for (int j = lane; j < L; j += 32) m1 = fmaxf(m1, row[j]);
        #pragma unroll
        for (int o = 16; o; o >>= 1) m1 = fmaxf(m1, __shfl_xor_sync(0xffffffffu, m1, o));

        float Z1 = 0.f;
        for (int j = lane; j < L; j += 32) Z1 += __expf(row[j] - m1);
        #pragma unroll
        for (int o = 16; o; o >>= 1) Z1 += __shfl_xor_sync(0xffffffffu, Z1, o);
        float invZ1 = __frcp_rn(Z1);

        float running = 0.f, m2 = -INFINITY;
        for (int jb = 0; jb < L; jb += 32) {
            int j = jb + lane;
            float s = (j < L) ? row[j] : 0.f;
            float e = (j < L) ? __expf(s - m1) : 0.f;
            float c = e;
            #pragma unroll
            for (int o = 1; o < 32; o <<= 1) {
                float t = __shfl_up_sync(0xffffffffu, c, o);
                if (lane >= o) c += t;
            }
            float cum = running + c;
            running += __shfl_sync(0xffffffffu, c, 31);
            if (j < L) {
                float rem = 1.f - cum * invZ1;
                float pos = (float)(qg - j);
                float dist = sqrtf(fmaxf(rem * pos, 0.f));
                float eff = fmaxf(__expf(gam * dist), 1e-5f);
                float s2 = s * eff;
                row[j] = s2;
                m2 = fmaxf(m2, s2);
            }
        }
        #pragma unroll
        for (int o = 16; o; o >>= 1) m2 = fmaxf(m2, __shfl_xor_sync(0xffffffffu, m2, o));

        float Z2 = 0.f;
        for (int j = lane; j < L; j += 32) Z2 += __expf(row[j] - m2);
        #pragma unroll
        for (int o = 16; o; o >>= 1) Z2 += __shfl_xor_sync(0xffffffffu, Z2, o);
        float invZ2 = __frcp_rn(Z2);

        float* grow = scores_out + ((size_t)bh * S_ + qg) * S_;
        for (int j4 = lane; j4 < S_/4; j4 += 32) {
            int j = j4 * 4;
            float4 sv = *(const float4*)&row[j];
            float4 p;
            p.x = (j+0 < L) ? __expf(sv.x - m2) * invZ2 : 0.f;
            p.y = (j+1 < L) ? __expf(sv.y - m2) * invZ2 : 0.f;
            p.z = (j+2 < L) ? __expf(sv.z - m2) * invZ2 : 0.f;
            p.w = (j+3 < L) ? __expf(sv.w - m2) * invZ2 : 0.f;
            *(float4*)&row[j] = p;              // for PV
            __stcs((float4*)&grow[j], p);       // streaming scores store
        }
    }

    // ---- PV: L-split across 16 warps; thread holds ctx[32 rows] for dim=lane ----
    float acc[32];
    #pragma unroll
    for (int r = 0; r < 32; r++) acc[r] = 0.f;

    for (int ch = 0; ch < nch; ch++) {
        int jb = ch * JC;
        __syncthreads();
        for (int f = tid; f < JC * 8; f += THREADS) {   // V natural [j][32]
            int j = f >> 3, d4 = f & 7;
            *(float4*)&sKV[j * 32 + d4 * 4] =
                *(const float4*)&Vp[(size_t)(jb + j) * DH_ + d4 * 4];
        }
        __syncthreads();
        // warp handles js [jb + warp*8, jb + warp*8 + 8) -> 2 float4 groups
        #pragma unroll
        for (int g = 0; g < 2; g++) {
            int jloc = warp * 8 + g * 4;
            int j = jb + jloc;
            float v0 = sKV[(jloc+0) * 32 + lane];
            float v1 = sKV[(jloc+1) * 32 + lane];
            float v2 = sKV[(jloc+2) * 32 + lane];
            float v3 = sKV[(jloc+3) * 32 + lane];
            #pragma unroll
            for (int r = 0; r < 32; r++) {
                float4 p4 = *(const float4*)&sS[(size_t)r * SS_STRIDE + j];
                float t = p4.x * v0 + p4.y * v1;
                t = fmaf(p4.z, v2, t);
                t = fmaf(p4.w, v3, t);
                acc[r] += t;
            }
        }
    }

    // ---- cross-warp reduction (16 -> 1) via 32 KB buffer ----
    #pragma unroll
    for (int step = 8; step >= 1; step >>= 1) {
        __syncthreads();
        if (warp >= step && warp < 2*step) {
            #pragma unroll
            for (int r = 0; r < 32; r++)
                sRed[(warp - step) * 1024 + r * 32 + lane] = acc[r];
        }
        __syncthreads();
        if (warp < step) {
            #pragma unroll
            for (int r = 0; r < 32; r++)
                acc[r] += sRed[warp * 1024 + r * 32 + lane];
        }
    }
    if (warp == 0) {
        #pragma unroll
        for (int r = 0; r < 32; r++)
            g_ctx[((size_t)(b * S_ + q0 + r)) * D_ + h * DH_ + lane] = acc[r];
    }
}

// ---------------------------------------------------------------------------
extern "C" void kernel_launch(void* const* d_in, const int* in_sizes, int n_in,
                              void* d_out, int out_size) {
    const float* q      = (const float*)d_in[0];
    const float* k      = (const float*)d_in[1];
    const float* v      = (const float*)d_in[2];
    const float* Wq     = (const float*)d_in[4];
    const float* bq     = (const float*)d_in[5];
    const float* Wv     = (const float*)d_in[6];
    const float* bv     = (const float*)d_in[7];
    const float* Wo     = (const float*)d_in[8];
    const float* bo     = (const float*)d_in[9];
    const float* gammas = (const float*)d_in[10];

    float* out    = (float*)d_out;                       // [B,S,D]
    float* scores = out + (size_t)B_ * S_ * D_;          // [B,H,S,S]

    float *Qp, *Kp, *Vp, *ctx;
    cudaGetSymbolAddress((void**)&Qp,  g_Qp);
    cudaGetSymbolAddress((void**)&Kp,  g_Kp);
    cudaGetSymbolAddress((void**)&Vp,  g_Vp);
    cudaGetSymbolAddress((void**)&ctx, g_ctx);

    dim3 ggrid(4, 128);
    gemm_bias_kernel<<<ggrid, 256>>>(q, Wq, bq, Qp, 1);
    gemm_bias_kernel<<<ggrid, 256>>>(k, Wq, bq, Kp, 1);
    gemm_bias_kernel<<<ggrid, 256>>>(v, Wv, bv, Vp, 1);

    cudaFuncSetAttribute(attn_kernel, cudaFuncAttributeMaxDynamicSharedMemorySize, SMEM_BYTES);
    attn_kernel<<<dim3(S_ / ROWS, BH_), THREADS, SMEM_BYTES>>>(gammas, scores);

    gemm_bias_kernel<<<ggrid, 256>>>(ctx, Wo, bo, out, 0);
}

// round 4
// speedup vs baseline: 1.7643x; 1.1104x over previous
#include <cuda_runtime.h>
#include <math.h>

#define B_ 8
#define S_ 1024
#define D_ 256
#define H_ 8
#define DH_ 32
#define BH_ (B_*H_)
#define ROWS 16
#define JC 128
#define SS_STRIDE 1028
#define THREADS 512

// Scratch (device globals: no allocation allowed)
__device__ float g_Qp[BH_*S_*DH_];   // [B,H,S,DH]
__device__ float g_Kp[BH_*S_*DH_];
__device__ float g_Vp[BH_*S_*DH_];
__device__ float g_ctx[B_*S_*D_];    // attention output, [B,S,D]

// ---------------------------------------------------------------------------
// GEMM: C[m,n] = sum_k A[m,k] * W[n,k] + bias[n]   (M=8192, N=K=256)
// ---------------------------------------------------------------------------
__global__ __launch_bounds__(256) void gemm_bias_kernel(
    const float* __restrict__ A, const float* __restrict__ W,
    const float* __restrict__ bias, float* __restrict__ C, int headLayout)
{
    __shared__ float sA[16][68];
    __shared__ float sW[16][68];
    const int K = D_;
    int tid = threadIdx.x;
    int tx = tid & 15, ty = tid >> 4;
    int m0 = blockIdx.y * 64, n0 = blockIdx.x * 64;
    int lr = tid >> 2, lc = (tid & 3) * 4;
    float acc[4][4] = {};
    for (int k0 = 0; k0 < K; k0 += 16) {
        float4 av = *(const float4*)&A[(size_t)(m0 + lr) * K + k0 + lc];
        float4 wv = *(const float4*)&W[(size_t)(n0 + lr) * K + k0 + lc];
        sA[lc+0][lr] = av.x; sA[lc+1][lr] = av.y; sA[lc+2][lr] = av.z; sA[lc+3][lr] = av.w;
        sW[lc+0][lr] = wv.x; sW[lc+1][lr] = wv.y; sW[lc+2][lr] = wv.z; sW[lc+3][lr] = wv.w;
        __syncthreads();
        #pragma unroll
        for (int kk = 0; kk < 16; kk++) {
            float4 a4 = *(const float4*)&sA[kk][ty*4];
            float4 b4 = *(const float4*)&sW[kk][tx*4];
            float a[4] = {a4.x, a4.y, a4.z, a4.w};
            float b[4] = {b4.x, b4.y, b4.z, b4.w};
            #pragma unroll
            for (int i = 0; i < 4; i++)
                #pragma unroll
                for (int j = 0; j < 4; j++)
                    acc[i][j] = fmaf(a[i], b[j], acc[i][j]);
        }
        __syncthreads();
    }
    #pragma unroll
    for (int i = 0; i < 4; i++) {
        int m = m0 + ty*4 + i;
        int bb = m >> 10, ss = m & 1023;
        #pragma unroll
        for (int j = 0; j < 4; j++) {
            int n = n0 + tx*4 + j;
            float val = acc[i][j] + bias[n];
            if (headLayout) {
                int h = n >> 5, dh = n & 31;
                C[(((size_t)(bb*H_ + h) * S_) + ss) * DH_ + dh] = val;
            } else {
                C[(size_t)m * D_ + n] = val;
            }
        }
    }
}

// ---------------------------------------------------------------------------
// Fused attention: per block = one (b,h) and 16 query rows, 512 threads.
// smem: sS[16][1028] | sQ[16][32] swz | sKV[128][32] (swz for K; reused as
// PV reduction buffer). 84 KB -> 2 CTAs/SM.
// ---------------------------------------------------------------------------
#define SQ_OFF   (ROWS * SS_STRIDE)
#define SKV_OFF  (SQ_OFF + ROWS * 32)
#define SMEM_FLOATS (SKV_OFF + JC * 32)
#define SMEM_BYTES (SMEM_FLOATS * 4)

__global__ __launch_bounds__(THREADS, 2) void attn_kernel(
    const float* __restrict__ gammas, float* __restrict__ scores_out)
{
    extern __shared__ float smem[];
    float* sS   = smem;
    float* sQ   = smem + SQ_OFF;
    float* sKV  = smem + SKV_OFF;
    float* sRed = sKV;                           // reused after PV mainloop
    int tid = threadIdx.x;
    int lane = tid & 31, warp = tid >> 5;        // 16 warps
    int bh = blockIdx.y;
    int q0 = blockIdx.x * ROWS;
    int h = bh & (H_ - 1);
    int b = bh >> 3;
    const float* Q  = g_Qp + (size_t)bh * S_ * DH_;
    const float* Kp = g_Kp + (size_t)bh * S_ * DH_;
    const float* Vp = g_Vp + (size_t)bh * S_ * DH_;

    // ---- stage Q (scaled), swizzled: d4e = d4 ^ ((r>>1)&7) ----
    if (tid < ROWS * 8) {
        int r = tid >> 3, d4 = tid & 7;
        float4 qv = *(const float4*)&Q[(size_t)(q0 + r) * DH_ + d4 * 4];
        const float sc = 0.17677669529663688f;
        qv.x *= sc; qv.y *= sc; qv.z *= sc; qv.w *= sc;
        *(float4*)&sQ[r * 32 + ((d4 ^ ((r >> 1) & 7)) << 2)] = qv;
    }

    int nch = (q0 + ROWS + JC - 1) / JC;

    // QK tiling: warp -> cols [warp*8, warp*8+8), all 16 rows; thread 2x2
    int rg = lane >> 2;               // 0..7 -> rows {2rg, 2rg+1}
    int cg = lane & 3;                // 0..3 -> cols {warp*8+2cg, +1}
    int r0 = rg * 2;
    int cbase = warp * 8 + cg * 2;
    int ck = (cbase >> 1) & 7;        // k swizzle key (same for col pair)

    // ---- QK^T into sS ----
    for (int ch = 0; ch < nch; ch++) {
        int jb = ch * JC;
        __syncthreads();
        // stage K chunk [j][d], swizzled d4e = d4 ^ ((j>>1)&7)
        for (int f = tid; f < JC * 8; f += THREADS) {
            int j = f >> 3, d4 = f & 7;
            float4 kv = *(const float4*)&Kp[(size_t)(jb + j) * DH_ + d4 * 4];
            *(float4*)&sKV[j * 32 + ((d4 ^ ((j >> 1) & 7)) << 2)] = kv;
        }
        __syncthreads();
        float acc00 = 0.f, acc01 = 0.f, acc10 = 0.f, acc11 = 0.f;
        #pragma unroll
        for (int d4 = 0; d4 < 8; d4++) {
            int qswz = (d4 ^ rg) << 2;
            float4 qa = *(const float4*)&sQ[r0 * 32 + qswz];
            float4 qb = *(const float4*)&sQ[(r0 + 1) * 32 + qswz];
            int kswz = (d4 ^ ck) << 2;
            float4 ka = *(const float4*)&sKV[cbase * 32 + kswz];
            float4 kb = *(const float4*)&sKV[(cbase + 1) * 32 + kswz];
            acc00 = fmaf(qa.x, ka.x, acc00); acc00 = fmaf(qa.y, ka.y, acc00);
            acc00 = fmaf(qa.z, ka.z, acc00); acc00 = fmaf(qa.w, ka.w, acc00);
            acc01 = fmaf(qa.x, kb.x, acc01); acc01 = fmaf(qa.y, kb.y, acc01);
            acc01 = fmaf(qa.z, kb.z, acc01); acc01 = fmaf(qa.w, kb.w, acc01);
            acc10 = fmaf(qb.x, ka.x, acc10); acc10 = fmaf(qb.y, ka.y, acc10);
            acc10 = fmaf(qb.z, ka.z, acc10); acc10 = fmaf(qb.w, ka.w, acc10);
            acc11 = fmaf(qb.x, kb.x, acc11); acc11 = fmaf(qb.y, kb.y, acc11);
            acc11 = fmaf(qb.z, kb.z, acc11); acc11 = fmaf(qb.w, kb.w, acc11);
        }
        *(float2*)&sS[(size_t)r0 * SS_STRIDE + jb + cbase] = make_float2(acc00, acc01);
        *(float2*)&sS[(size_t)(r0 + 1) * SS_STRIDE + jb + cbase] = make_float2(acc10, acc11);
    }
    __syncthreads();

    // ---- row-wise (1 row per warp): softmax, scan, decay, softmax, write ----
    {
        float gam = -fabsf(gammas[h]);
        int r = warp;
        int qg = q0 + r;
        int L = qg + 1;
        float* row = sS + (size_t)r * SS_STRIDE;

        float m1 = -INFINITY;
        for (int j = lane; j < L; j += 32) m1 = fmaxf(m1, row[j]);
        #pragma unroll
        for (int o = 16; o; o >>= 1) m1 = fmaxf(m1, __shfl_xor_sync(0xffffffffu, m1, o));

        float Z1 = 0.f;
        for (int j = lane; j < L; j += 32) Z1 += __expf(row[j] - m1);
        #pragma unroll
        for (int o = 16; o; o >>= 1) Z1 += __shfl_xor_sync(0xffffffffu, Z1, o);
        float invZ1 = __frcp_rn(Z1);

        float running = 0.f, m2 = -INFINITY;
        for (int jb = 0; jb < L; jb += 32) {
            int j = jb + lane;
            float s = (j < L) ? row[j] : 0.f;
            float e = (j < L) ? __expf(s - m1) : 0.f;
            float c = e;
            #pragma unroll
            for (int o = 1; o < 32; o <<= 1) {
                float t = __shfl_up_sync(0xffffffffu, c, o);
                if (lane >= o) c += t;
            }
            float cum = running + c;
            running += __shfl_sync(0xffffffffu, c, 31);
            if (j < L) {
                float rem = 1.f - cum * invZ1;
                float pos = (float)(qg - j);
                float dist = sqrtf(fmaxf(rem * pos, 0.f));
                float eff = fmaxf(__expf(gam * dist), 1e-5f);
                float s2 = s * eff;
                row[j] = s2;
                m2 = fmaxf(m2, s2);
            }
        }
        #pragma unroll
        for (int o = 16; o; o >>= 1) m2 = fmaxf(m2, __shfl_xor_sync(0xffffffffu, m2, o));

        float Z2 = 0.f;
        for (int j = lane; j < L; j += 32) Z2 += __expf(row[j] - m2);
        #pragma unroll
        for (int o = 16; o; o >>= 1) Z2 += __shfl_xor_sync(0xffffffffu, Z2, o);
        float invZ2 = __frcp_rn(Z2);

        float* grow = scores_out + ((size_t)bh * S_ + qg) * S_;
        for (int j4 = lane; j4 < S_/4; j4 += 32) {
            int j = j4 * 4;
            float4 sv = *(const float4*)&row[j];
            float4 p;
            p.x = (j+0 < L) ? __expf(sv.x - m2) * invZ2 : 0.f;
            p.y = (j+1 < L) ? __expf(sv.y - m2) * invZ2 : 0.f;
            p.z = (j+2 < L) ? __expf(sv.z - m2) * invZ2 : 0.f;
            p.w = (j+3 < L) ? __expf(sv.w - m2) * invZ2 : 0.f;
            *(float4*)&row[j] = p;              // for PV
            __stcs((float4*)&grow[j], p);       // streaming scores store
        }
    }

    // ---- PV: L-split across 16 warps; thread holds ctx[16 rows], dim=lane ----
    float acc[ROWS];
    #pragma unroll
    for (int r = 0; r < ROWS; r++) acc[r] = 0.f;

    for (int ch = 0; ch < nch; ch++) {
        int jb = ch * JC;
        __syncthreads();
        for (int f = tid; f < JC * 8; f += THREADS) {   // V natural [j][32]
            int j = f >> 3, d4 = f & 7;
            *(float4*)&sKV[j * 32 + d4 * 4] =
                *(const float4*)&Vp[(size_t)(jb + j) * DH_ + d4 * 4];
        }
        __syncthreads();
        #pragma unroll
        for (int g = 0; g < 2; g++) {
            int jloc = warp * 8 + g * 4;
            int j = jb + jloc;
            float v0 = sKV[(jloc+0) * 32 + lane];
            float v1 = sKV[(jloc+1) * 32 + lane];
            float v2 = sKV[(jloc+2) * 32 + lane];
            float v3 = sKV[(jloc+3) * 32 + lane];
            #pragma unroll
            for (int r = 0; r < ROWS; r++) {
                float4 p4 = *(const float4*)&sS[(size_t)r * SS_STRIDE + j];
                float t = p4.x * v0 + p4.y * v1;
                t = fmaf(p4.z, v2, t);
                t = fmaf(p4.w, v3, t);
                acc[r] += t;
            }
        }
    }

    // ---- cross-warp reduction (16 -> 1) via reused sKV buffer (16 KB) ----
    #pragma unroll
    for (int step = 8; step >= 1; step >>= 1) {
        __syncthreads();
        if (warp >= step && warp < 2*step) {
            #pragma unroll
            for (int r = 0; r < ROWS; r++)
                sRed[(warp - step) * (ROWS*32) + r * 32 + lane] = acc[r];
        }
        __syncthreads();
        if (warp < step) {
            #pragma unroll
            for (int r = 0; r < ROWS; r++)
                acc[r] += sRed[warp * (ROWS*32) + r * 32 + lane];
        }
    }
    if (warp == 0) {
        #pragma unroll
        for (int r = 0; r < ROWS; r++)
            g_ctx[((size_t)(b * S_ + q0 + r)) * D_ + h * DH_ + lane] = acc[r];
    }
}

// ---------------------------------------------------------------------------
extern "C" void kernel_launch(void* const* d_in, const int* in_sizes, int n_in,
                              void* d_out, int out_size) {
    const float* q      = (const float*)d_in[0];
    const float* k      = (const float*)d_in[1];
    const float* v      = (const float*)d_in[2];
    const float* Wq     = (const float*)d_in[4];
    const float* bq     = (const float*)d_in[5];
    const float* Wv     = (const float*)d_in[6];
    const float* bv     = (const float*)d_in[7];
    const float* Wo     = (const float*)d_in[8];
    const float* bo     = (const float*)d_in[9];
    const float* gammas = (const float*)d_in[10];

    float* out    = (float*)d_out;                       // [B,S,D]
    float* scores = out + (size_t)B_ * S_ * D_;          // [B,H,S,S]

    float *Qp, *Kp, *Vp, *ctx;
    cudaGetSymbolAddress((void**)&Qp,  g_Qp);
    cudaGetSymbolAddress((void**)&Kp,  g_Kp);
    cudaGetSymbolAddress((void**)&Vp,  g_Vp);
    cudaGetSymbolAddress((void**)&ctx, g_ctx);

    dim3 ggrid(4, 128);
    gemm_bias_kernel<<<ggrid, 256>>>(q, Wq, bq, Qp, 1);
    gemm_bias_kernel<<<ggrid, 256>>>(k, Wq, bq, Kp, 1);
    gemm_bias_kernel<<<ggrid, 256>>>(v, Wv, bv, Vp, 1);

    cudaFuncSetAttribute(attn_kernel, cudaFuncAttributeMaxDynamicSharedMemorySize, SMEM_BYTES);
    attn_kernel<<<dim3(S_ / ROWS, BH_), THREADS, SMEM_BYTES>>>(gammas, scores);

    gemm_bias_kernel<<<ggrid, 256>>>(ctx, Wo, bo, out, 0);
}

// round 5
// speedup vs baseline: 1.9792x; 1.1218x over previous
#include <cuda_runtime.h>
#include <math.h>

#define B_ 8
#define S_ 1024
#define D_ 256
#define H_ 8
#define DH_ 32
#define BH_ (B_*H_)
#define ROWS 16
#define JC 128
#define SS_STRIDE 1028
#define THREADS 512

// Scratch (device globals: no allocation allowed)
__device__ float g_Qp[BH_*S_*DH_];   // [B,H,S,DH]
__device__ float g_Kp[BH_*S_*DH_];
__device__ float g_Vp[BH_*S_*DH_];
__device__ float g_ctx[B_*S_*D_];    // attention output, [B,S,D]

// ---------------------------------------------------------------------------
// GEMM body: C[m,n] = sum_k A[m,k] * W[n,k] + bias[n]   (M=8192, N=K=256)
// ---------------------------------------------------------------------------
__device__ __forceinline__ void gemm_body(
    const float* __restrict__ A, const float* __restrict__ W,
    const float* __restrict__ bias, float* __restrict__ C, int headLayout)
{
    __shared__ float sA[16][68];
    __shared__ float sW[16][68];
    const int K = D_;
    int tid = threadIdx.x;
    int tx = tid & 15, ty = tid >> 4;
    int m0 = blockIdx.y * 64, n0 = blockIdx.x * 64;
    int lr = tid >> 2, lc = (tid & 3) * 4;
    float acc[4][4] = {};
    for (int k0 = 0; k0 < K; k0 += 16) {
        float4 av = *(const float4*)&A[(size_t)(m0 + lr) * K + k0 + lc];
        float4 wv = *(const float4*)&W[(size_t)(n0 + lr) * K + k0 + lc];
        sA[lc+0][lr] = av.x; sA[lc+1][lr] = av.y; sA[lc+2][lr] = av.z; sA[lc+3][lr] = av.w;
        sW[lc+0][lr] = wv.x; sW[lc+1][lr] = wv.y; sW[lc+2][lr] = wv.z; sW[lc+3][lr] = wv.w;
        __syncthreads();
        #pragma unroll
        for (int kk = 0; kk < 16; kk++) {
            float4 a4 = *(const float4*)&sA[kk][ty*4];
            float4 b4 = *(const float4*)&sW[kk][tx*4];
            float a[4] = {a4.x, a4.y, a4.z, a4.w};
            float b[4] = {b4.x, b4.y, b4.z, b4.w};
            #pragma unroll
            for (int i = 0; i < 4; i++)
                #pragma unroll
                for (int j = 0; j < 4; j++)
                    acc[i][j] = fmaf(a[i], b[j], acc[i][j]);
        }
        __syncthreads();
    }
    #pragma unroll
    for (int i = 0; i < 4; i++) {
        int m = m0 + ty*4 + i;
        int bb = m >> 10, ss = m & 1023;
        #pragma unroll
        for (int j = 0; j < 4; j++) {
            int n = n0 + tx*4 + j;
            float val = acc[i][j] + bias[n];
            if (headLayout) {
                int h = n >> 5, dh = n & 31;
                C[(((size_t)(bb*H_ + h) * S_) + ss) * DH_ + dh] = val;
            } else {
                C[(size_t)m * D_ + n] = val;
            }
        }
    }
}

// 3 projection GEMMs in one launch (z selects)
__global__ __launch_bounds__(256) void proj3_kernel(
    const float* __restrict__ q, const float* __restrict__ k, const float* __restrict__ v,
    const float* __restrict__ Wq, const float* __restrict__ bq,
    const float* __restrict__ Wv, const float* __restrict__ bv,
    float* __restrict__ Qp, float* __restrict__ Kp, float* __restrict__ Vp)
{
    int z = blockIdx.z;
    const float* A = (z == 0) ? q : (z == 1) ? k : v;
    const float* W = (z == 2) ? Wv : Wq;
    const float* bias = (z == 2) ? bv : bq;
    float* C = (z == 0) ? Qp : (z == 1) ? Kp : Vp;
    gemm_body(A, W, bias, C, 1);
}

__global__ __launch_bounds__(256) void gemm_bias_kernel(
    const float* __restrict__ A, const float* __restrict__ W,
    const float* __restrict__ bias, float* __restrict__ C)
{
    gemm_body(A, W, bias, C, 0);
}

// ---------------------------------------------------------------------------
// Fused attention: per block = one (b,h) and 16 query rows, 512 threads.
// ---------------------------------------------------------------------------
#define SQ_OFF   (ROWS * SS_STRIDE)
#define SKV_OFF  (SQ_OFF + ROWS * 32)
#define SMEM_FLOATS (SKV_OFF + JC * 32)
#define SMEM_BYTES (SMEM_FLOATS * 4)

__global__ __launch_bounds__(THREADS, 2) void attn_kernel(
    const float* __restrict__ gammas, float* __restrict__ scores_out)
{
    extern __shared__ float smem[];
    float* sS   = smem;
    float* sQ   = smem + SQ_OFF;
    float* sKV  = smem + SKV_OFF;
    float* sRed = sKV;                           // reused after PV mainloop
    int tid = threadIdx.x;
    int lane = tid & 31, warp = tid >> 5;        // 16 warps
    int bh = blockIdx.y;
    int q0 = blockIdx.x * ROWS;
    int h = bh & (H_ - 1);
    int b = bh >> 3;
    const float* Q  = g_Qp + (size_t)bh * S_ * DH_;
    const float* Kp = g_Kp + (size_t)bh * S_ * DH_;
    const float* Vp = g_Vp + (size_t)bh * S_ * DH_;

    // ---- stage Q (scaled), swizzled: d4e = d4 ^ ((r>>1)&7) ----
    if (tid < ROWS * 8) {
        int r = tid >> 3, d4 = tid & 7;
        float4 qv = *(const float4*)&Q[(size_t)(q0 + r) * DH_ + d4 * 4];
        const float sc = 0.17677669529663688f;
        qv.x *= sc; qv.y *= sc; qv.z *= sc; qv.w *= sc;
        *(float4*)&sQ[r * 32 + ((d4 ^ ((r >> 1) & 7)) << 2)] = qv;
    }

    int nch = (q0 + ROWS + JC - 1) / JC;

    // QK tiling: warp -> cols [warp*8, warp*8+8), all 16 rows; thread 2x2
    int rg = lane >> 2;
    int cg = lane & 3;
    int r0 = rg * 2;
    int cbase = warp * 8 + cg * 2;
    int ck = (cbase >> 1) & 7;

    // ---- QK^T into sS ----
    for (int ch = 0; ch < nch; ch++) {
        int jb = ch * JC;
        __syncthreads();
        for (int f = tid; f < JC * 8; f += THREADS) {
            int j = f >> 3, d4 = f & 7;
            float4 kv = *(const float4*)&Kp[(size_t)(jb + j) * DH_ + d4 * 4];
            *(float4*)&sKV[j * 32 + ((d4 ^ ((j >> 1) & 7)) << 2)] = kv;
        }
        __syncthreads();
        float acc00 = 0.f, acc01 = 0.f, acc10 = 0.f, acc11 = 0.f;
        #pragma unroll
        for (int d4 = 0; d4 < 8; d4++) {
            int qswz = (d4 ^ rg) << 2;
            float4 qa = *(const float4*)&sQ[r0 * 32 + qswz];
            float4 qb = *(const float4*)&sQ[(r0 + 1) * 32 + qswz];
            int kswz = (d4 ^ ck) << 2;
            float4 ka = *(const float4*)&sKV[cbase * 32 + kswz];
            float4 kb = *(const float4*)&sKV[(cbase + 1) * 32 + kswz];
            acc00 = fmaf(qa.x, ka.x, acc00); acc00 = fmaf(qa.y, ka.y, acc00);
            acc00 = fmaf(qa.z, ka.z, acc00); acc00 = fmaf(qa.w, ka.w, acc00);
            acc01 = fmaf(qa.x, kb.x, acc01); acc01 = fmaf(qa.y, kb.y, acc01);
            acc01 = fmaf(qa.z, kb.z, acc01); acc01 = fmaf(qa.w, kb.w, acc01);
            acc10 = fmaf(qb.x, ka.x, acc10); acc10 = fmaf(qb.y, ka.y, acc10);
            acc10 = fmaf(qb.z, ka.z, acc10); acc10 = fmaf(qb.w, ka.w, acc10);
            acc11 = fmaf(qb.x, kb.x, acc11); acc11 = fmaf(qb.y, kb.y, acc11);
            acc11 = fmaf(qb.z, kb.z, acc11); acc11 = fmaf(qb.w, kb.w, acc11);
        }
        *(float2*)&sS[(size_t)r0 * SS_STRIDE + jb + cbase] = make_float2(acc00, acc01);
        *(float2*)&sS[(size_t)(r0 + 1) * SS_STRIDE + jb + cbase] = make_float2(acc10, acc11);
    }
    __syncthreads();

    // ---- row phase (1 row/warp), no max subtraction, 3 vectorized passes ----
    {
        float gam = -fabsf(gammas[h]);
        int qg = q0 + warp;
        int L = qg + 1;
        float* row = sS + (size_t)warp * SS_STRIDE;

        // Pass 1: Z1 = sum exp(s)
        float Z1 = 0.f;
        for (int j = lane * 4; j < L; j += 128) {
            float4 sv = *(const float4*)&row[j];
            if (j + 0 < L) Z1 += __expf(sv.x);
            if (j + 1 < L) Z1 += __expf(sv.y);
            if (j + 2 < L) Z1 += __expf(sv.z);
            if (j + 3 < L) Z1 += __expf(sv.w);
        }
        #pragma unroll
        for (int o = 16; o; o >>= 1) Z1 += __shfl_xor_sync(0xffffffffu, Z1, o);
        float invZ1 = __frcp_rn(Z1);

        // Pass 2: scan cum(exp), decay, p=exp(s*eff) stored unnormalized; Z2
        float running = 0.f, Z2 = 0.f;
        int nb = (L + 127) >> 7;
        for (int bi = 0; bi < nb; bi++) {
            int j = bi * 128 + lane * 4;
            float4 sv = *(const float4*)&row[j];
            float e0 = (j + 0 < L) ? __expf(sv.x) : 0.f;
            float e1 = (j + 1 < L) ? __expf(sv.y) : 0.f;
            float e2 = (j + 2 < L) ? __expf(sv.z) : 0.f;
            float e3 = (j + 3 < L) ? __expf(sv.w) : 0.f;
            float p1 = e0 + e1, p2 = p1 + e2, p3 = p2 + e3;
            float c = p3;
            #pragma unroll
            for (int o = 1; o < 32; o <<= 1) {
                float t = __shfl_up_sync(0xffffffffu, c, o);
                if (lane >= o) c += t;
            }
            float excl = running + c - p3;
            running += __shfl_sync(0xffffffffu, c, 31);
            float4 out = {0.f, 0.f, 0.f, 0.f};
            if (j + 0 < L) {
                float rem = 1.f - (excl + e0) * invZ1;
                float dist = sqrtf(fmaxf(rem * (float)(qg - j), 0.f));
                float eff = fmaxf(__expf(gam * dist), 1e-5f);
                out.x = __expf(sv.x * eff); Z2 += out.x;
            }
            if (j + 1 < L) {
                float rem = 1.f - (excl + p1) * invZ1;
                float dist = sqrtf(fmaxf(rem * (float)(qg - j - 1), 0.f));
                float eff = fmaxf(__expf(gam * dist), 1e-5f);
                out.y = __expf(sv.y * eff); Z2 += out.y;
            }
            if (j + 2 < L) {
                float rem = 1.f - (excl + p2) * invZ1;
                float dist = sqrtf(fmaxf(rem * (float)(qg - j - 2), 0.f));
                float eff = fmaxf(__expf(gam * dist), 1e-5f);
                out.z = __expf(sv.z * eff); Z2 += out.z;
            }
            if (j + 3 < L) {
                float rem = 1.f - (excl + p3) * invZ1;
                float dist = sqrtf(fmaxf(rem * (float)(qg - j - 3), 0.f));
                float eff = fmaxf(__expf(gam * dist), 1e-5f);
                out.w = __expf(sv.w * eff); Z2 += out.w;
            }
            *(float4*)&row[j] = out;
        }
        #pragma unroll
        for (int o = 16; o; o >>= 1) Z2 += __shfl_xor_sync(0xffffffffu, Z2, o);
        float invZ2 = __frcp_rn(Z2);

        // Pass 3: normalize, write row (for PV) + gmem scores (masked zeros)
        float* grow = scores_out + ((size_t)bh * S_ + qg) * S_;
        for (int j = lane * 4; j < S_; j += 128) {
            float4 pv = *(const float4*)&row[j];
            float4 p;
            p.x = (j + 0 < L) ? pv.x * invZ2 : 0.f;
            p.y = (j + 1 < L) ? pv.y * invZ2 : 0.f;
            p.z = (j + 2 < L) ? pv.z * invZ2 : 0.f;
            p.w = (j + 3 < L) ? pv.w * invZ2 : 0.f;
            *(float4*)&row[j] = p;
            __stcs((float4*)&grow[j], p);
        }
    }

    // ---- PV: L-split across 16 warps; thread holds ctx[16 rows], dim=lane ----
    float acc[ROWS];
    #pragma unroll
    for (int r = 0; r < ROWS; r++) acc[r] = 0.f;

    for (int ch = 0; ch < nch; ch++) {
        int jb = ch * JC;
        __syncthreads();
        for (int f = tid; f < JC * 8; f += THREADS) {
            int j = f >> 3, d4 = f & 7;
            *(float4*)&sKV[j * 32 + d4 * 4] =
                *(const float4*)&Vp[(size_t)(jb + j) * DH_ + d4 * 4];
        }
        __syncthreads();
        #pragma unroll
        for (int g = 0; g < 2; g++) {
            int jloc = warp * 8 + g * 4;
            int j = jb + jloc;
            float v0 = sKV[(jloc+0) * 32 + lane];
            float v1 = sKV[(jloc+1) * 32 + lane];
            float v2 = sKV[(jloc+2) * 32 + lane];
            float v3 = sKV[(jloc+3) * 32 + lane];
            #pragma unroll
            for (int r = 0; r < ROWS; r++) {
                float4 p4 = *(const float4*)&sS[(size_t)r * SS_STRIDE + j];
                float t = p4.x * v0 + p4.y * v1;
                t = fmaf(p4.z, v2, t);
                t = fmaf(p4.w, v3, t);
                acc[r] += t;
            }
        }
    }

    // ---- cross-warp reduction (16 -> 1) via reused sKV buffer ----
    #pragma unroll
    for (int step = 8; step >= 1; step >>= 1) {
        __syncthreads();
        if (warp >= step && warp < 2*step) {
            #pragma unroll
            for (int r = 0; r < ROWS; r++)
                sRed[(warp - step) * (ROWS*32) + r * 32 + lane] = acc[r];
        }
        __syncthreads();
        if (warp < step) {
            #pragma unroll
            for (int r = 0; r < ROWS; r++)
                acc[r] += sRed[warp * (ROWS*32) + r * 32 + lane];
        }
    }
    if (warp == 0) {
        #pragma unroll
        for (int r = 0; r < ROWS; r++)
            g_ctx[((size_t)(b * S_ + q0 + r)) * D_ + h * DH_ + lane] = acc[r];
    }
}

// ---------------------------------------------------------------------------
extern "C" void kernel_launch(void* const* d_in, const int* in_sizes, int n_in,
                              void* d_out, int out_size) {
    const float* q      = (const float*)d_in[0];
    const float* k      = (const float*)d_in[1];
    const float* v      = (const float*)d_in[2];
    const float* Wq     = (const float*)d_in[4];
    const float* bq     = (const float*)d_in[5];
    const float* Wv     = (const float*)d_in[6];
    const float* bv     = (const float*)d_in[7];
    const float* Wo     = (const float*)d_in[8];
    const float* bo     = (const float*)d_in[9];
    const float* gammas = (const float*)d_in[10];

    float* out    = (float*)d_out;                       // [B,S,D]
    float* scores = out + (size_t)B_ * S_ * D_;          // [B,H,S,S]

    float *Qp, *Kp, *Vp, *ctx;
    cudaGetSymbolAddress((void**)&Qp,  g_Qp);
    cudaGetSymbolAddress((void**)&Kp,  g_Kp);
    cudaGetSymbolAddress((void**)&Vp,  g_Vp);
    cudaGetSymbolAddress((void**)&ctx, g_ctx);

    proj3_kernel<<<dim3(4, 128, 3), 256>>>(q, k, v, Wq, bq, Wv, bv, Qp, Kp, Vp);

    cudaFuncSetAttribute(attn_kernel, cudaFuncAttributeMaxDynamicSharedMemorySize, SMEM_BYTES);
    attn_kernel<<<dim3(S_ / ROWS, BH_), THREADS, SMEM_BYTES>>>(gammas, scores);

    gemm_bias_kernel<<<dim3(4, 128), 256>>>(ctx, Wo, bo, out);
}